// round 12
// baseline (speedup 1.0000x reference)
#include <cuda_runtime.h>
#include <math.h>

#define BB 2
#define HH 12
#define NN 2048
#define DD 64
#define BH (BB*HH)            // 24
#define RTOT (BH*NN)          // 49152
#define TILE 128
#define NT (NN/TILE)          // 16
#define TRI ((NT*(NT+1))/2)   // 136

// scratch (allocation-free rule: __device__ globals)
__device__ float g_qn[(size_t)RTOT*DD];        // 12.6 MB
__device__ float g_kn[(size_t)RTOT*DD];        // 12.6 MB
__device__ float g_ncp[(size_t)BH*NT*NN];      // 3.1 MB column-sum partials [bh][it][j]

// ---- packed f32x2 helpers -------------------------------------------------
__device__ __forceinline__ unsigned long long pk2(float x, float y) {
    unsigned long long r;
    asm("mov.b64 %0, {%1,%2};" : "=l"(r) : "f"(x), "f"(y));
    return r;
}
__device__ __forceinline__ float2 upk(unsigned long long v) {
    float2 r;
    asm("mov.b64 {%0,%1}, %2;" : "=f"(r.x), "=f"(r.y) : "l"(v));
    return r;
}
__device__ __forceinline__ unsigned long long fma2(unsigned long long a,
                                                   unsigned long long b,
                                                   unsigned long long c) {
    unsigned long long d;
    asm("fma.rn.f32x2 %0, %1, %2, %3;" : "=l"(d) : "l"(a), "l"(b), "l"(c));
    return d;
}
__device__ __forceinline__ float fast_lg2(float x) {
    float r; asm("lg2.approx.f32 %0, %1;" : "=f"(r) : "f"(x)); return r;
}
__device__ __forceinline__ float fast_ex2(float x) {
    float r; asm("ex2.approx.f32 %0, %1;" : "=f"(r) : "f"(x)); return r;
}

// ---------------------------------------------------------------------------
// Kernel A: L2-normalize q and k rows (1 warp per row), zero g_ncp.
// ---------------------------------------------------------------------------
__global__ __launch_bounds__(256) void knorm_kernel(const float* __restrict__ q,
                                                    const float* __restrict__ k)
{
    int gt   = blockIdx.x*256 + threadIdx.x;
    if (gt < BH*NT*NN) g_ncp[gt] = 0.0f;

    int gw   = gt >> 5;
    int lane = threadIdx.x & 31;
    const float* src; float* dst; int row;
    if (gw < RTOT) { row = gw;        src = q; dst = g_qn; }
    else           { row = gw - RTOT; src = k; dst = g_kn; }

    float2 v = ((const float2*)(src + (size_t)row*DD))[lane];
    float ss = v.x*v.x + v.y*v.y;
    #pragma unroll
    for (int o = 16; o; o >>= 1) ss += __shfl_xor_sync(0xffffffffu, ss, o);
    float inv = 1.0f / sqrtf(fmaxf(ss, 1e-24f));
    float2 r2; r2.x = v.x*inv; r2.y = v.y*inv;
    ((float2*)(dst + (size_t)row*DD))[lane] = r2;
}

// ---------------------------------------------------------------------------
// Kernel B: per lower-triangular 128x128 tile:
//   S = (1 + acos(clip(qn.kn)))^(-65.5), causal-masked (zeros above diag in
//   the diagonal tile), stored fp32 into W region (read back by C);
//   per-tile column partial sums. Mainloop: packed fma.rn.f32x2.
// ---------------------------------------------------------------------------
#define SMEM_B ((2*64*132 + 16*128)*4)

__global__ __launch_bounds__(256, 2) void kscore_kernel(float* __restrict__ W)
{
    extern __shared__ float sm[];
    float* qs = sm;                 // [64][132]  (d-major, padded)
    float* ks = sm + 64*132;        // [64][132]
    float* cp = sm + 2*64*132;      // [16][128]  column partials per ty-group

    int bh  = blockIdx.x / TRI;
    int lin = blockIdx.x % TRI;
    int it  = (int)((sqrtf(8.0f*(float)lin + 1.0f) - 1.0f)*0.5f);
    while ((it+1)*(it+2)/2 <= lin) ++it;
    while (it*(it+1)/2 > lin)      --it;
    int jt  = lin - it*(it+1)/2;    // jt <= it : lower triangle only

    int tid = threadIdx.x;

    // cooperative transposed load of q/k tiles
    {
        const float4* q4 = (const float4*)(g_qn + ((size_t)bh*NN + (size_t)it*TILE)*DD);
        const float4* k4 = (const float4*)(g_kn + ((size_t)bh*NN + (size_t)jt*TILE)*DD);
        for (int x = tid; x < TILE*16; x += 256) {
            int m = x >> 4, d4 = x & 15;
            float4 a = q4[m*16 + d4];
            qs[(d4*4+0)*132 + m] = a.x;
            qs[(d4*4+1)*132 + m] = a.y;
            qs[(d4*4+2)*132 + m] = a.z;
            qs[(d4*4+3)*132 + m] = a.w;
            float4 b = k4[m*16 + d4];
            ks[(d4*4+0)*132 + m] = b.x;
            ks[(d4*4+1)*132 + m] = b.y;
            ks[(d4*4+2)*132 + m] = b.z;
            ks[(d4*4+3)*132 + m] = b.w;
        }
    }
    __syncthreads();

    int ty = tid >> 4, tx = tid & 15;
    unsigned long long acc2[8][4];
    #pragma unroll
    for (int r = 0; r < 8; r++)
        #pragma unroll
        for (int c = 0; c < 4; c++) acc2[r][c] = 0ULL;

    #pragma unroll 4
    for (int kk = 0; kk < 64; kk++) {
        float4 a0 = *(const float4*)&qs[kk*132 + ty*8];
        float4 a1 = *(const float4*)&qs[kk*132 + ty*8 + 4];
        ulonglong2 bl0 = *(const ulonglong2*)&ks[kk*132 + tx*8];
        ulonglong2 bl1 = *(const ulonglong2*)&ks[kk*132 + tx*8 + 4];
        unsigned long long b2[4] = {bl0.x, bl0.y, bl1.x, bl1.y};
        unsigned long long aa[8];
        aa[0] = pk2(a0.x, a0.x); aa[1] = pk2(a0.y, a0.y);
        aa[2] = pk2(a0.z, a0.z); aa[3] = pk2(a0.w, a0.w);
        aa[4] = pk2(a1.x, a1.x); aa[5] = pk2(a1.y, a1.y);
        aa[6] = pk2(a1.z, a1.z); aa[7] = pk2(a1.w, a1.w);
        #pragma unroll
        for (int r = 0; r < 8; r++)
            #pragma unroll
            for (int c = 0; c < 4; c++)
                acc2[r][c] = fma2(aa[r], b2[c], acc2[r][c]);
    }

    int ib = it*TILE + ty*8;
    int jb = jt*TILE + tx*8;
    float colp[8];
    #pragma unroll
    for (int c = 0; c < 8; c++) colp[c] = 0.0f;

    #pragma unroll
    for (int r = 0; r < 8; r++) {
        int i = ib + r;
        float w[8];
        #pragma unroll
        for (int c2 = 0; c2 < 4; c2++) {
            float2 u = upk(acc2[r][c2]);
            float cv[2] = {u.x, u.y};
            #pragma unroll
            for (int h = 0; h < 2; h++) {
                int c = c2*2 + h;
                int j = jb + c;
                float s = 0.0f;
                if (j <= i) {
                    float cc = fminf(fmaxf(cv[h], -1.0f), 1.0f);
                    float g  = acosf(cc);
                    s = fast_ex2(-65.5f * fast_lg2(1.0f + g));   // (1+g)^(-65.5)
                }
                w[c] = s;
                colp[c] += s;
            }
        }
        float* wp = W + ((size_t)bh*NN + (size_t)i)*NN + jb;
        *(float4*)(wp)     = make_float4(w[0],w[1],w[2],w[3]);
        *(float4*)(wp + 4) = make_float4(w[4],w[5],w[6],w[7]);
    }

    #pragma unroll
    for (int c = 0; c < 8; c++) cp[ty*128 + tx*8 + c] = colp[c];
    __syncthreads();
    if (tid < 128) {
        float s = 0.0f;
        #pragma unroll
        for (int t = 0; t < 16; t++) s += cp[t*128 + tid];
        g_ncp[((size_t)bh*NT + it)*NN + (size_t)jt*TILE + tid] = s; // unique slot -> deterministic
    }
}

// ---------------------------------------------------------------------------
// Kernel C: per (bh, 128-row block rb):
//   prologue: rsnc[j] = rsqrt(sum_it g_ncp[...,j])               (smem)
//   phase 1 : rowsum_i = sum_j S_ij * rsnc_j  -> s_inv[row]
//   phase 2 : per tile jt<=rb: w = S*rsnc*inv written to global W (streaming
//             store, W is write-once) and staged transposed in smem;
//             o += w @ v with 8x4 register tiling (fma.rn.f32x2).
//             Tiles jt>rb: zero-fill global W (streaming store).
// ---------------------------------------------------------------------------
#define SMEM_C ((NN + 128*68 + 128*132 + 128)*4)

__global__ __launch_bounds__(256, 2) void kout_kernel(float* __restrict__ W,
                                                      const float* __restrict__ v,
                                                      float* __restrict__ out)
{
    extern __shared__ float sm[];
    float* s_rsnc = sm;                            // [2048]
    float* s_v    = sm + NN;                       // [128][68] padded
    float* s_w    = sm + NN + 128*68;              // [128 k][132 rows] transposed
    float* s_inv  = sm + NN + 128*68 + 128*132;    // [128]

    // heavy blocks (large rb) get the lowest bids -> first wave
    int rb = 15 - (blockIdx.x / BH);
    int bh = blockIdx.x % BH;
    int tid = threadIdx.x;

    float* Wb = W + ((size_t)bh*NN + (size_t)rb*TILE)*NN;   // block's 128 rows
    float4* Wb4 = (float4*)Wb;

    // prologue: column-sum reduce + rsqrt
    for (int j = tid; j < NN; j += 256) {
        float s = 0.0f;
        #pragma unroll
        for (int t = 0; t < NT; t++) s += g_ncp[((size_t)bh*NT + t)*NN + j];
        s_rsnc[j] = rsqrtf(s);
    }
    __syncthreads();

    // phase 1: row sums (S is zero above the diagonal within the diagonal tile)
    {
        int w = tid >> 5, lane = tid & 31;
        int len4 = (rb + 1) * 32;
        for (int r16 = 0; r16 < 16; r16++) {
            int row = w*16 + r16;
            const float4* Sp = (const float4*)(Wb + (size_t)row*NN);
            float p = 0.0f;
            for (int j4 = lane; j4 < len4; j4 += 32) {
                float4 s4 = Sp[j4];
                float4 rn = *(const float4*)&s_rsnc[j4*4];
                p += s4.x*rn.x + s4.y*rn.y + s4.z*rn.z + s4.w*rn.w;
            }
            #pragma unroll
            for (int o = 16; o; o >>= 1) p += __shfl_xor_sync(0xffffffffu, p, o);
            if (lane == 0) s_inv[row] = 1.0f / p;
        }
    }
    __syncthreads();

    // phase 2
    int ty = tid >> 4, tx = tid & 15;       // ty: 8-row group, tx: 4-d group
    int wrp = tid >> 5, lane = tid & 31;
    int rr  = lane >> 2, k4l = lane & 3;    // warp = 8 rows x 4 float4-chunks

    unsigned long long acc2[4][4];
    #pragma unroll
    for (int a = 0; a < 4; a++)
        #pragma unroll
        for (int b = 0; b < 4; b++) acc2[a][b] = 0ULL;

    for (int jt = 0; jt <= rb; jt++) {
        // 2a: w = S*rsnc*inv -> global W (streaming) + transposed smem stage
        #pragma unroll 2
        for (int it = 0; it < 16; it++) {
            int wc  = it*8 + wrp;                 // 0..127
            int k4  = (wc & 7)*4 + k4l;           // 0..31
            int row = (wc >> 3)*8 + rr;           // 0..127
            float4 s4 = Wb4[(size_t)row*(NN/4) + jt*32 + k4];
            float4 rn = *(const float4*)&s_rsnc[jt*TILE + k4*4];
            float iv  = s_inv[row];
            float4 w4;
            w4.x = s4.x*rn.x*iv; w4.y = s4.y*rn.y*iv;
            w4.z = s4.z*rn.z*iv; w4.w = s4.w*rn.w*iv;
            __stwt(&Wb4[(size_t)row*(NN/4) + jt*32 + k4], w4);   // write-once: bypass L2
            int kb = k4*4;
            s_w[(kb+0)*132 + row] = w4.x;
            s_w[(kb+1)*132 + row] = w4.y;
            s_w[(kb+2)*132 + row] = w4.z;
            s_w[(kb+3)*132 + row] = w4.w;
        }
        {
            const float4* v4 = (const float4*)(v + ((size_t)bh*NN + (size_t)jt*TILE)*DD);
            for (int idx = tid; idx < TILE*16; idx += 256) {
                int jr = idx >> 4, d4 = idx & 15;
                *(float4*)&s_v[jr*68 + d4*4] = v4[jr*16 + d4];
            }
        }
        __syncthreads();

        // 2b: o += w @ v   (128 k-steps; 8 rows x 4 d per thread, f32x2 pairs)
        #pragma unroll 4
        for (int k = 0; k < TILE; k++) {
            ulonglong2 wA = *(const ulonglong2*)&s_w[k*132 + ty*8];
            ulonglong2 wB = *(const ulonglong2*)&s_w[k*132 + ty*8 + 4];
            unsigned long long wp[4] = {wA.x, wA.y, wB.x, wB.y};
            float4 vv = *(const float4*)&s_v[k*68 + tx*4];
            unsigned long long vd[4];
            vd[0] = pk2(vv.x, vv.x); vd[1] = pk2(vv.y, vv.y);
            vd[2] = pk2(vv.z, vv.z); vd[3] = pk2(vv.w, vv.w);
            #pragma unroll
            for (int rp = 0; rp < 4; rp++)
                #pragma unroll
                for (int d = 0; d < 4; d++)
                    acc2[rp][d] = fma2(wp[rp], vd[d], acc2[rp][d]);
        }
        __syncthreads();
    }

    // zero-fill fully-masked tiles (upper triangle) — streaming stores
    for (int jt = rb + 1; jt < NT; jt++) {
        float4 z = make_float4(0.f, 0.f, 0.f, 0.f);
        for (int idx = tid; idx < 4096; idx += 256) {
            int row = idx >> 5, k4 = idx & 31;
            __stwt(&Wb4[(size_t)row*(NN/4) + jt*32 + k4], z);
        }
    }

    // store output: rows ty*8 + 2rp + {0,1}, cols tx*4..+3
    #pragma unroll
    for (int rp = 0; rp < 4; rp++) {
        float2 u0 = upk(acc2[rp][0]);
        float2 u1 = upk(acc2[rp][1]);
        float2 u2 = upk(acc2[rp][2]);
        float2 u3 = upk(acc2[rp][3]);
        int row0 = rb*TILE + ty*8 + 2*rp;
        float* o0 = out + ((size_t)bh*NN + (size_t)row0)*DD + tx*4;
        __stwt((float4*)o0,        make_float4(u0.x, u1.x, u2.x, u3.x));
        __stwt((float4*)(o0 + DD), make_float4(u0.y, u1.y, u2.y, u3.y));
    }
}

// ---------------------------------------------------------------------------
extern "C" void kernel_launch(void* const* d_in, const int* in_sizes, int n_in,
                              void* d_out, int out_size)
{
    const float* q = (const float*)d_in[0];
    const float* k = (const float*)d_in[1];
    const float* v = (const float*)d_in[2];
    // d_in[3] = attn_mask (causal, hardcoded)

    float* out = (float*)d_out;                       // [BH, N, D]
    float* W   = out + (size_t)RTOT * DD;             // [BH, N, N] attn_weights

    cudaFuncSetAttribute(kscore_kernel, cudaFuncAttributeMaxDynamicSharedMemorySize, SMEM_B);
    cudaFuncSetAttribute(kout_kernel,   cudaFuncAttributeMaxDynamicSharedMemorySize, SMEM_C);

    knorm_kernel<<<(2*RTOT)/8, 256>>>(q, k);             // normalize + zero partials
    kscore_kernel<<<BH*TRI, 256, SMEM_B>>>(W);           // 3264 lower-tri tiles
    kout_kernel<<<BH*NT, 256, SMEM_C>>>(W, v, out);      // 384 blocks of 128 rows
}

// round 13
// speedup vs baseline: 1.1184x; 1.1184x over previous
#include <cuda_runtime.h>
#include <math.h>

#define BB 2
#define HH 12
#define NN 2048
#define DD 64
#define BH (BB*HH)            // 24
#define RTOT (BH*NN)          // 49152
#define TILE 128
#define NT (NN/TILE)          // 16
#define TRI ((NT*(NT+1))/2)   // 136

// scratch (allocation-free rule: __device__ globals)
__device__ float g_qn[(size_t)RTOT*DD];        // 12.6 MB
__device__ float g_kn[(size_t)RTOT*DD];        // 12.6 MB
__device__ float g_ncp[(size_t)BH*NT*NN];      // 3.1 MB column-sum partials [bh][it][j]
__device__ float g_rsnc[(size_t)BH*NN];        // 0.2 MB  rsqrt(column sums)
__device__ float g_inv[(size_t)BH*NN];         // 0.2 MB  1/rowsum

// ---- packed f32x2 helpers -------------------------------------------------
__device__ __forceinline__ unsigned long long pk2(float x, float y) {
    unsigned long long r;
    asm("mov.b64 %0, {%1,%2};" : "=l"(r) : "f"(x), "f"(y));
    return r;
}
__device__ __forceinline__ float2 upk(unsigned long long v) {
    float2 r;
    asm("mov.b64 {%0,%1}, %2;" : "=f"(r.x), "=f"(r.y) : "l"(v));
    return r;
}
__device__ __forceinline__ unsigned long long fma2(unsigned long long a,
                                                   unsigned long long b,
                                                   unsigned long long c) {
    unsigned long long d;
    asm("fma.rn.f32x2 %0, %1, %2, %3;" : "=l"(d) : "l"(a), "l"(b), "l"(c));
    return d;
}
__device__ __forceinline__ float fast_lg2(float x) {
    float r; asm("lg2.approx.f32 %0, %1;" : "=f"(r) : "f"(x)); return r;
}
__device__ __forceinline__ float fast_ex2(float x) {
    float r; asm("ex2.approx.f32 %0, %1;" : "=f"(r) : "f"(x)); return r;
}

// ---------------------------------------------------------------------------
// Kernel A: L2-normalize q and k rows (1 warp per row), zero g_ncp.
// ---------------------------------------------------------------------------
__global__ __launch_bounds__(256) void knorm_kernel(const float* __restrict__ q,
                                                    const float* __restrict__ k)
{
    int gt   = blockIdx.x*256 + threadIdx.x;
    if (gt < BH*NT*NN) g_ncp[gt] = 0.0f;

    int gw   = gt >> 5;
    int lane = threadIdx.x & 31;
    const float* src; float* dst; int row;
    if (gw < RTOT) { row = gw;        src = q; dst = g_qn; }
    else           { row = gw - RTOT; src = k; dst = g_kn; }

    float2 v = ((const float2*)(src + (size_t)row*DD))[lane];
    float ss = v.x*v.x + v.y*v.y;
    #pragma unroll
    for (int o = 16; o; o >>= 1) ss += __shfl_xor_sync(0xffffffffu, ss, o);
    float inv = 1.0f / sqrtf(fmaxf(ss, 1e-24f));
    float2 r2; r2.x = v.x*inv; r2.y = v.y*inv;
    ((float2*)(dst + (size_t)row*DD))[lane] = r2;
}

// ---------------------------------------------------------------------------
// Kernel B (unchanged from R6-passing): per lower-triangular 128x128 tile:
//   S = (1 + acos(clip(qn.kn)))^(-65.5), causal-masked, stored fp32 into the
//   W region; per-tile column partial sums. Mainloop: packed fma.rn.f32x2.
// ---------------------------------------------------------------------------
#define SMEM_B ((2*64*132 + 16*128)*4)

__global__ __launch_bounds__(256, 2) void kscore_kernel(float* __restrict__ W)
{
    extern __shared__ float sm[];
    float* qs = sm;                 // [64][132]  (d-major, padded)
    float* ks = sm + 64*132;        // [64][132]
    float* cp = sm + 2*64*132;      // [16][128]  column partials per ty-group

    int bh  = blockIdx.x / TRI;
    int lin = blockIdx.x % TRI;
    int it  = (int)((sqrtf(8.0f*(float)lin + 1.0f) - 1.0f)*0.5f);
    while ((it+1)*(it+2)/2 <= lin) ++it;
    while (it*(it+1)/2 > lin)      --it;
    int jt  = lin - it*(it+1)/2;    // jt <= it : lower triangle only

    int tid = threadIdx.x;

    {
        const float4* q4 = (const float4*)(g_qn + ((size_t)bh*NN + (size_t)it*TILE)*DD);
        const float4* k4 = (const float4*)(g_kn + ((size_t)bh*NN + (size_t)jt*TILE)*DD);
        for (int x = tid; x < TILE*16; x += 256) {
            int m = x >> 4, d4 = x & 15;
            float4 a = q4[m*16 + d4];
            qs[(d4*4+0)*132 + m] = a.x;
            qs[(d4*4+1)*132 + m] = a.y;
            qs[(d4*4+2)*132 + m] = a.z;
            qs[(d4*4+3)*132 + m] = a.w;
            float4 b = k4[m*16 + d4];
            ks[(d4*4+0)*132 + m] = b.x;
            ks[(d4*4+1)*132 + m] = b.y;
            ks[(d4*4+2)*132 + m] = b.z;
            ks[(d4*4+3)*132 + m] = b.w;
        }
    }
    __syncthreads();

    int ty = tid >> 4, tx = tid & 15;
    unsigned long long acc2[8][4];
    #pragma unroll
    for (int r = 0; r < 8; r++)
        #pragma unroll
        for (int c = 0; c < 4; c++) acc2[r][c] = 0ULL;

    #pragma unroll 4
    for (int kk = 0; kk < 64; kk++) {
        float4 a0 = *(const float4*)&qs[kk*132 + ty*8];
        float4 a1 = *(const float4*)&qs[kk*132 + ty*8 + 4];
        ulonglong2 bl0 = *(const ulonglong2*)&ks[kk*132 + tx*8];
        ulonglong2 bl1 = *(const ulonglong2*)&ks[kk*132 + tx*8 + 4];
        unsigned long long b2[4] = {bl0.x, bl0.y, bl1.x, bl1.y};
        unsigned long long aa[8];
        aa[0] = pk2(a0.x, a0.x); aa[1] = pk2(a0.y, a0.y);
        aa[2] = pk2(a0.z, a0.z); aa[3] = pk2(a0.w, a0.w);
        aa[4] = pk2(a1.x, a1.x); aa[5] = pk2(a1.y, a1.y);
        aa[6] = pk2(a1.z, a1.z); aa[7] = pk2(a1.w, a1.w);
        #pragma unroll
        for (int r = 0; r < 8; r++)
            #pragma unroll
            for (int c = 0; c < 4; c++)
                acc2[r][c] = fma2(aa[r], b2[c], acc2[r][c]);
    }

    int ib = it*TILE + ty*8;
    int jb = jt*TILE + tx*8;
    float colp[8];
    #pragma unroll
    for (int c = 0; c < 8; c++) colp[c] = 0.0f;

    #pragma unroll
    for (int r = 0; r < 8; r++) {
        int i = ib + r;
        float w[8];
        #pragma unroll
        for (int c2 = 0; c2 < 4; c2++) {
            float2 u = upk(acc2[r][c2]);
            float cv[2] = {u.x, u.y};
            #pragma unroll
            for (int h = 0; h < 2; h++) {
                int c = c2*2 + h;
                int j = jb + c;
                float s = 0.0f;
                if (j <= i) {
                    float cc = fminf(fmaxf(cv[h], -1.0f), 1.0f);
                    float g  = acosf(cc);
                    s = fast_ex2(-65.5f * fast_lg2(1.0f + g));   // (1+g)^(-65.5)
                }
                w[c] = s;
                colp[c] += s;
            }
        }
        float* wp = W + ((size_t)bh*NN + (size_t)i)*NN + jb;
        *(float4*)(wp)     = make_float4(w[0],w[1],w[2],w[3]);
        *(float4*)(wp + 4) = make_float4(w[4],w[5],w[6],w[7]);
    }

    #pragma unroll
    for (int c = 0; c < 8; c++) cp[ty*128 + tx*8 + c] = colp[c];
    __syncthreads();
    if (tid < 128) {
        float s = 0.0f;
        #pragma unroll
        for (int t = 0; t < 16; t++) s += cp[t*128 + tid];
        g_ncp[((size_t)bh*NT + it)*NN + (size_t)jt*TILE + tid] = s;
    }
}

// ---------------------------------------------------------------------------
// Kernel B2 (tiny): rsnc[bh][j] = rsqrt(sum_it g_ncp[bh][it][j])
// ---------------------------------------------------------------------------
__global__ __launch_bounds__(256) void kcolnorm_kernel()
{
    int gi = blockIdx.x*256 + threadIdx.x;     // bh*NN + j
    int bh = gi >> 11, j = gi & (NN-1);
    float s = 0.0f;
    #pragma unroll
    for (int t = 0; t < NT; t++) s += g_ncp[((size_t)bh*NT + t)*NN + j];
    g_rsnc[gi] = rsqrtf(s);
}

// ---------------------------------------------------------------------------
// Kernel C1: per (bh, 128-row block rb), SINGLE pass over S:
//   per tile jt<=rb: stage u = S*rsnc transposed in smem; accumulate in-smem
//   rowsums (deterministic, conflict-free) AND o_unnorm += u @ v (8x4 register
//   tiling, fma.rn.f32x2). After the loop: inv = 1/rowsum -> g_inv,
//   o = o_unnorm * inv -> out.  (No W writes here; W produced by C2.)
// ---------------------------------------------------------------------------
#define SMEM_C ((NN + 128*68 + 128*132 + 256 + 128)*4)

__global__ __launch_bounds__(256, 2) void kout_kernel(const float* __restrict__ Wsrc,
                                                      const float* __restrict__ v,
                                                      float* __restrict__ out)
{
    extern __shared__ float sm[];
    float* s_rsnc = sm;                              // [2048]
    float* s_v    = sm + NN;                         // [128][68] padded
    float* s_w    = sm + NN + 128*68;                // [128 k][132 rows] transposed u
    float* s_ra   = sm + NN + 128*68 + 128*132;      // [2][128] rowsum halves
    float* s_inv  = sm + NN + 128*68 + 128*132 + 256;// [128]

    int rb = 15 - (blockIdx.x / BH);   // heavy blocks first
    int bh = blockIdx.x % BH;
    int tid = threadIdx.x;

    const float4* Wb4 = (const float4*)(Wsrc + ((size_t)bh*NN + (size_t)rb*TILE)*NN);

    // load rsnc row + zero rowsum accumulators
    for (int j = tid; j < NN; j += 256) s_rsnc[j] = g_rsnc[(size_t)bh*NN + j];
    if (tid < 256) s_ra[tid] = 0.0f;
    __syncthreads();

    int ty = tid >> 4, tx = tid & 15;       // 2b mapping: 8-row x 4-d per thread
    int wrp = tid >> 5, lane = tid & 31;
    int rr  = lane >> 2, k4l = lane & 3;    // 2a mapping: warp = 8 rows x 4 chunks
    int rowown = tid & 127, half = tid >> 7; // rowsum mapping

    unsigned long long acc2[4][4];
    #pragma unroll
    for (int a = 0; a < 4; a++)
        #pragma unroll
        for (int b = 0; b < 4; b++) acc2[a][b] = 0ULL;

    for (int jt = 0; jt <= rb; jt++) {
        // 2a: u = S*rsnc -> transposed smem stage (no global write)
        #pragma unroll 2
        for (int it = 0; it < 16; it++) {
            int wc  = it*8 + wrp;                 // 0..127
            int k4  = (wc & 7)*4 + k4l;           // 0..31
            int row = (wc >> 3)*8 + rr;           // 0..127
            float4 s4 = Wb4[(size_t)row*(NN/4) + jt*32 + k4];
            float4 rn = *(const float4*)&s_rsnc[jt*TILE + k4*4];
            int kb = k4*4;
            s_w[(kb+0)*132 + row] = s4.x*rn.x;
            s_w[(kb+1)*132 + row] = s4.y*rn.y;
            s_w[(kb+2)*132 + row] = s4.z*rn.z;
            s_w[(kb+3)*132 + row] = s4.w*rn.w;
        }
        // stage v tile
        {
            const float4* v4 = (const float4*)(v + ((size_t)bh*NN + (size_t)jt*TILE)*DD);
            for (int idx = tid; idx < TILE*16; idx += 256) {
                int jr = idx >> 4, d4 = idx & 15;
                *(float4*)&s_v[jr*68 + d4*4] = v4[jr*16 + d4];
            }
        }
        __syncthreads();

        // rowsum partials from staged u (conflict-free: banks (4k+row)%32)
        {
            float a = 0.0f;
            int k0 = half*64;
            #pragma unroll 8
            for (int k = 0; k < 64; k++) a += s_w[(k0+k)*132 + rowown];
            s_ra[half*128 + rowown] += a;     // single owner -> deterministic
        }

        // 2b: o_unnorm += u @ v   (128 k-steps; 8 rows x 4 d per thread)
        #pragma unroll 4
        for (int k = 0; k < TILE; k++) {
            ulonglong2 wA = *(const ulonglong2*)&s_w[k*132 + ty*8];
            ulonglong2 wB = *(const ulonglong2*)&s_w[k*132 + ty*8 + 4];
            unsigned long long wp[4] = {wA.x, wA.y, wB.x, wB.y};
            float4 vv = *(const float4*)&s_v[k*68 + tx*4];
            unsigned long long vd[4];
            vd[0] = pk2(vv.x, vv.x); vd[1] = pk2(vv.y, vv.y);
            vd[2] = pk2(vv.z, vv.z); vd[3] = pk2(vv.w, vv.w);
            #pragma unroll
            for (int rp = 0; rp < 4; rp++)
                #pragma unroll
                for (int d = 0; d < 4; d++)
                    acc2[rp][d] = fma2(wp[rp], vd[d], acc2[rp][d]);
        }
        __syncthreads();
    }

    // inv = 1/rowsum; publish for C2
    if (tid < 128) {
        float inv = 1.0f / (s_ra[tid] + s_ra[128 + tid]);
        s_inv[tid] = inv;
        g_inv[(size_t)bh*NN + rb*TILE + tid] = inv;
    }
    __syncthreads();

    // store output scaled by inv: rows ty*8 + 2rp + {0,1}, cols tx*4..+3
    #pragma unroll
    for (int rp = 0; rp < 4; rp++) {
        int rl = ty*8 + 2*rp;
        float i0 = s_inv[rl], i1 = s_inv[rl + 1];
        float2 u0 = upk(acc2[rp][0]);
        float2 u1 = upk(acc2[rp][1]);
        float2 u2 = upk(acc2[rp][2]);
        float2 u3 = upk(acc2[rp][3]);
        int row0 = rb*TILE + rl;
        float* o0 = out + ((size_t)bh*NN + (size_t)row0)*DD + tx*4;
        *(float4*)o0        = make_float4(u0.x*i0, u1.x*i0, u2.x*i0, u3.x*i0);
        *(float4*)(o0 + DD) = make_float4(u0.y*i1, u1.y*i1, u2.y*i1, u3.y*i1);
    }
}

// ---------------------------------------------------------------------------
// Kernel C2: pure streaming finalize of W, one block per row:
//   j4 < lim (S data present): W = S * rsnc_j * inv_i   (in place)
//   j4 >= lim (masked region) : W = 0
//   (B wrote zeros above the diagonal inside the diagonal tile, so no
//    per-element predicates are needed.)
// ---------------------------------------------------------------------------
__global__ __launch_bounds__(256) void kfinal_kernel(float* __restrict__ W)
{
    int i  = blockIdx.x & (NN-1);
    int bh = blockIdx.x >> 11;
    float iv = g_inv[(size_t)bh*NN + i];
    const float4* rn4 = (const float4*)(g_rsnc + (size_t)bh*NN);
    float4* row = (float4*)(W + ((size_t)bh*NN + (size_t)i)*NN);
    int lim = ((i >> 7) + 1) * 32;          // float4s containing S data
    int tid = threadIdx.x;

    #pragma unroll
    for (int h = 0; h < 2; h++) {
        int j4 = tid + h*256;
        if (j4 < lim) {
            float4 s = row[j4];
            float4 r = rn4[j4];
            row[j4] = make_float4(s.x*r.x*iv, s.y*r.y*iv, s.z*r.z*iv, s.w*r.w*iv);
        } else {
            row[j4] = make_float4(0.f, 0.f, 0.f, 0.f);
        }
    }
}

// ---------------------------------------------------------------------------
extern "C" void kernel_launch(void* const* d_in, const int* in_sizes, int n_in,
                              void* d_out, int out_size)
{
    const float* q = (const float*)d_in[0];
    const float* k = (const float*)d_in[1];
    const float* v = (const float*)d_in[2];
    // d_in[3] = attn_mask (causal, hardcoded)

    float* out = (float*)d_out;                       // [BH, N, D]
    float* W   = out + (size_t)RTOT * DD;             // [BH, N, N] attn_weights

    cudaFuncSetAttribute(kscore_kernel, cudaFuncAttributeMaxDynamicSharedMemorySize, SMEM_B);
    cudaFuncSetAttribute(kout_kernel,   cudaFuncAttributeMaxDynamicSharedMemorySize, SMEM_C);

    knorm_kernel<<<(2*RTOT)/8, 256>>>(q, k);          // normalize + zero partials
    kscore_kernel<<<BH*TRI, 256, SMEM_B>>>(W);        // 3264 lower-tri tiles -> S
    kcolnorm_kernel<<<BH*NN/256, 256>>>();            // rsnc
    kout_kernel<<<BH*NT, 256, SMEM_C>>>(W, v, out);   // single-pass o + inv
    kfinal_kernel<<<BH*NN, 256>>>(W);                 // streaming W finalize + zeros
}